// round 3
// baseline (speedup 1.0000x reference)
#include <cuda_runtime.h>

#define ULL unsigned long long

// ---------------- scratch (static device globals; no dynamic alloc) ----------------
__device__ float  g_xg[104857600];      // [256][1024][400] precomputed input gates (+bias)
__device__ ULL    g_W2hh[100 * 200];    // [k][j] packed pairs (W_hh[2j][k], W_hh[2j+1][k])
__device__ float4 g_W4ih[64 * 104];     // [k][j] (W_ih[4j+c][k]); j in [100,104) zero pad
__device__ float4 g_bias4[100];         // (b_ih + b_hh) grouped by 4

// ---------------- f32x2 packed-FMA helpers (Blackwell FFMA2) ----------------
__device__ __forceinline__ ULL pk(float x, float y) {
    ULL r; asm("mov.b64 %0,{%1,%2};" : "=l"(r) : "f"(x), "f"(y)); return r;
}
__device__ __forceinline__ float2 upk(ULL v) {
    float2 r; asm("mov.b64 {%0,%1},%2;" : "=f"(r.x), "=f"(r.y) : "l"(v)); return r;
}
__device__ __forceinline__ ULL fma2(ULL a, ULL b, ULL c) {
    ULL d; asm("fma.rn.f32x2 %0,%1,%2,%3;" : "=l"(d) : "l"(a), "l"(b), "l"(c)); return d;
}

__device__ __forceinline__ float sigf(float x) {
    float e = __expf(-x);
    return __fdividef(1.f, 1.f + e);
}
__device__ __forceinline__ float tahf(float x) {
    float e = __expf(2.f * x);
    return 1.f - __fdividef(2.f, e + 1.f);
}

// ---------------- prep: repack weights into GEMM-friendly layouts ----------------
__global__ void prep_kernel(const float* __restrict__ Wih, const float* __restrict__ Whh,
                            const float* __restrict__ bih, const float* __restrict__ bhh) {
    int tid = blockIdx.x * blockDim.x + threadIdx.x;
    int stride = gridDim.x * blockDim.x;
    for (int i = tid; i < 100 * 200; i += stride) {
        int k = i / 200, j = i % 200;
        g_W2hh[i] = pk(Whh[(2 * j) * 100 + k], Whh[(2 * j + 1) * 100 + k]);
    }
    for (int i = tid; i < 64 * 104; i += stride) {
        int k = i / 104, j = i % 104;
        float4 v = make_float4(0.f, 0.f, 0.f, 0.f);
        if (j < 100) {
            v.x = Wih[(4 * j + 0) * 64 + k];
            v.y = Wih[(4 * j + 1) * 64 + k];
            v.z = Wih[(4 * j + 2) * 64 + k];
            v.w = Wih[(4 * j + 3) * 64 + k];
        }
        g_W4ih[i] = v;
    }
    for (int i = tid; i < 100; i += stride) {
        float4 v;
        v.x = bih[4 * i + 0] + bhh[4 * i + 0];
        v.y = bih[4 * i + 1] + bhh[4 * i + 1];
        v.z = bih[4 * i + 2] + bhh[4 * i + 2];
        v.w = bih[4 * i + 3] + bhh[4 * i + 3];
        g_bias4[i] = v;
    }
}

// ---------------- phase 1: xg[r][g] = bias[g] + sum_d x[r][d] * W_ih[g][d] ----------------
// grid 4096 blocks x 416 threads; block does 64 rows x 400 gates.
// thread (rg = tid/104, j = tid%104): 16 rows x 4 gates (float4 along g), f32x2 math.
__global__ __launch_bounds__(416, 1) void xgemm_kernel(const float* __restrict__ x) {
    extern __shared__ char smem[];
    float4* sW4 = (float4*)smem;                       // 64*104 float4 = 106496 B
    ULL*    sxd = (ULL*)(smem + 64 * 104 * 16);        // 64*64 dup pairs = 32768 B

    int tid = threadIdx.x;
    for (int i = tid; i < 64 * 104; i += 416) sW4[i] = g_W4ih[i];
    const float* xb = x + (size_t)blockIdx.x * (64 * 64);
    for (int i = tid; i < 64 * 64; i += 416) { float v = xb[i]; sxd[i] = pk(v, v); }
    __syncthreads();

    int rg = tid / 104;
    int j  = tid % 104;

    ULL acc01[16], acc23[16];
#pragma unroll
    for (int r = 0; r < 16; r++) { acc01[r] = 0ull; acc23[r] = 0ull; }

    const ULL* xr = sxd + rg * 16 * 64;
#pragma unroll 2
    for (int k = 0; k < 64; k++) {
        float4 wv = sW4[k * 104 + j];
        ULL w01 = pk(wv.x, wv.y);
        ULL w23 = pk(wv.z, wv.w);
#pragma unroll
        for (int r = 0; r < 16; r++) {
            ULL xv = xr[r * 64 + k];
            acc01[r] = fma2(w01, xv, acc01[r]);
            acc23[r] = fma2(w23, xv, acc23[r]);
        }
    }
    if (j < 100) {
        float4 bv = g_bias4[j];
        size_t row0 = (size_t)blockIdx.x * 64 + rg * 16;
#pragma unroll
        for (int r = 0; r < 16; r++) {
            float2 a = upk(acc01[r]);
            float2 b = upk(acc23[r]);
            float4 o = make_float4(a.x + bv.x, a.y + bv.y, b.x + bv.z, b.y + bv.w);
            *(float4*)(g_xg + (row0 + r) * 400 + 4 * j) = o;
        }
    }
}

// ---------------- phase 2: sequential LSTM recurrence + fused FC head ----------------
// 128 blocks x 224 threads; block owns batches (2*blk, 2*blk+1). W_hh in SMEM (160 KB).
// thread j<200 computes gate pair (2j, 2j+1) for BOTH batches (W reuse in regs),
// then remaps to (batch, unit) for the pointwise cell update; c lives in a register.
__global__ __launch_bounds__(224, 1) void lstm_kernel(const float* __restrict__ h0,
                                                      const float* __restrict__ c0,
                                                      const float* __restrict__ Wfc,
                                                      const float* __restrict__ bfc,
                                                      float* __restrict__ out) {
    extern __shared__ char smem[];
    ULL*   sW2  = (ULL*)smem;                 // [100][200] pairs = 160000 B
    ULL*   shd0 = (ULL*)(smem + 160000);      // h batch0 duplicated pairs [100]
    ULL*   shd1 = (ULL*)(smem + 160800);      // h batch1 duplicated pairs [100]
    float* gs   = (float*)(smem + 161600);    // gates [2][400]
    float* red  = (float*)(smem + 164800);    // FC reduction [2]

    const int t  = threadIdx.x;
    const int b0 = blockIdx.x * 2;

    for (int i = t; i < 20000; i += 224) sW2[i] = g_W2hh[i];
    if (t < 2) red[t] = 0.f;

    const int ub = (t < 100) ? 0 : 1;
    const int uu = t - ub * 100;

    float c_reg = 0.f, h_last = 0.f;
    if (t < 200) {
        float hv = h0[(b0 + ub) * 100 + uu];
        c_reg    = c0[(b0 + ub) * 100 + uu];
        (ub ? shd1 : shd0)[uu] = pk(hv, hv);
    }
    __syncthreads();

    const float* xp0 = g_xg + (size_t)(b0)     * 1024 * 400 + 2 * t;
    const float* xp1 = g_xg + (size_t)(b0 + 1) * 1024 * 400 + 2 * t;
    float2 px0 = make_float2(0.f, 0.f), px1 = make_float2(0.f, 0.f);
    if (t < 200) { px0 = *(const float2*)xp0; px1 = *(const float2*)xp1; }

    for (int step = 0; step < 1024; step++) {
        if (t < 200) {
            ULL a0 = pk(px0.x, px0.y);   // xg init already includes biases
            ULL a1 = pk(px1.x, px1.y);
            if (step < 1023) {           // prefetch next step's xg (hides DRAM latency)
                px0 = *(const float2*)(xp0 + (size_t)(step + 1) * 400);
                px1 = *(const float2*)(xp1 + (size_t)(step + 1) * 400);
            }
            const ULL* wr = sW2 + t;
#pragma unroll 10
            for (int k = 0; k < 100; k++) {
                ULL w2 = wr[k * 200];     // conflict-free: lanes consecutive
                a0 = fma2(w2, shd0[k], a0);  // broadcast
                a1 = fma2(w2, shd1[k], a1);  // broadcast
            }
            ((float2*)gs)[t]       = upk(a0);   // gates[b0][2t..2t+1]
            ((float2*)gs)[200 + t] = upk(a1);   // gates[b1][2t..2t+1]
        }
        __syncthreads();
        if (t < 200) {
            const float* gb = gs + ub * 400;
            float gi = gb[uu], gf = gb[100 + uu], gg = gb[200 + uu], go = gb[300 + uu];
            float i_ = sigf(gi);
            float f_ = sigf(gf);
            float g_ = tahf(gg);
            float o_ = sigf(go);
            c_reg = f_ * c_reg + i_ * g_;
            float h = o_ * tahf(c_reg);
            h_last = h;
            (ub ? shd1 : shd0)[uu] = pk(h, h);
        }
        __syncthreads();
    }

    // fused FC head: out[b] = dot(h_T[b], W_fc) + b_fc
    if (t < 200) atomicAdd(&red[ub], h_last * Wfc[uu]);
    __syncthreads();
    if (t < 2) out[b0 + t] = red[t] + bfc[0];
}

// ---------------- launch ----------------
extern "C" void kernel_launch(void* const* d_in, const int* in_sizes, int n_in,
                              void* d_out, int out_size) {
    const float* x   = (const float*)d_in[0];
    const float* h0  = (const float*)d_in[1];
    const float* c0  = (const float*)d_in[2];
    const float* Wih = (const float*)d_in[3];
    const float* Whh = (const float*)d_in[4];
    const float* bih = (const float*)d_in[5];
    const float* bhh = (const float*)d_in[6];
    const float* Wfc = (const float*)d_in[7];
    const float* bfc = (const float*)d_in[8];
    float* out = (float*)d_out;

    cudaFuncSetAttribute(xgemm_kernel, cudaFuncAttributeMaxDynamicSharedMemorySize, 139264);
    cudaFuncSetAttribute(lstm_kernel,  cudaFuncAttributeMaxDynamicSharedMemorySize, 164864);

    prep_kernel<<<64, 256>>>(Wih, Whh, bih, bhh);
    xgemm_kernel<<<4096, 416, 139264>>>(x);
    lstm_kernel<<<128, 224, 164864>>>(h0, c0, Wfc, bfc, out);
}

// round 5
// speedup vs baseline: 1.4522x; 1.4522x over previous
#include <cuda_runtime.h>

#define ULL unsigned long long

// ---------------- scratch (static device globals; no dynamic alloc) ----------------
__device__ float  g_xg[104857600];      // [256][1024][400] precomputed input gates (+bias)
__device__ ULL    g_W2hh[100 * 200];    // [k][j] packed pairs (W_hh[2j][k], W_hh[2j+1][k])
__device__ float4 g_W4ih[64 * 104];     // [k][j] (W_ih[4j+c][k]); j in [100,104) zero pad
__device__ float4 g_bias4[100];         // (b_ih + b_hh) grouped by 4

// ---------------- f32x2 packed-FMA helpers (Blackwell FFMA2) ----------------
__device__ __forceinline__ ULL pk(float x, float y) {
    ULL r; asm("mov.b64 %0,{%1,%2};" : "=l"(r) : "f"(x), "f"(y)); return r;
}
__device__ __forceinline__ float2 upk(ULL v) {
    float2 r; asm("mov.b64 {%0,%1},%2;" : "=f"(r.x), "=f"(r.y) : "l"(v)); return r;
}
__device__ __forceinline__ ULL fma2(ULL a, ULL b, ULL c) {
    ULL d; asm("fma.rn.f32x2 %0,%1,%2,%3;" : "=l"(d) : "l"(a), "l"(b), "l"(c)); return d;
}

__device__ __forceinline__ float sigf(float x) {
    float e = __expf(-x);
    return __fdividef(1.f, 1.f + e);
}
__device__ __forceinline__ float tahf(float x) {
    float e = __expf(2.f * x);
    return 1.f - __fdividef(2.f, e + 1.f);
}

// ---------------- prep: repack weights into GEMM-friendly layouts ----------------
__global__ void prep_kernel(const float* __restrict__ Wih, const float* __restrict__ Whh,
                            const float* __restrict__ bih, const float* __restrict__ bhh) {
    int tid = blockIdx.x * blockDim.x + threadIdx.x;
    int stride = gridDim.x * blockDim.x;
    for (int i = tid; i < 100 * 200; i += stride) {
        int k = i / 200, j = i % 200;
        g_W2hh[i] = pk(Whh[(2 * j) * 100 + k], Whh[(2 * j + 1) * 100 + k]);
    }
    for (int i = tid; i < 64 * 104; i += stride) {
        int k = i / 104, j = i % 104;
        float4 v = make_float4(0.f, 0.f, 0.f, 0.f);
        if (j < 100) {
            v.x = Wih[(4 * j + 0) * 64 + k];
            v.y = Wih[(4 * j + 1) * 64 + k];
            v.z = Wih[(4 * j + 2) * 64 + k];
            v.w = Wih[(4 * j + 3) * 64 + k];
        }
        g_W4ih[i] = v;
    }
    for (int i = tid; i < 100; i += stride) {
        float4 v;
        v.x = bih[4 * i + 0] + bhh[4 * i + 0];
        v.y = bih[4 * i + 1] + bhh[4 * i + 1];
        v.z = bih[4 * i + 2] + bhh[4 * i + 2];
        v.w = bih[4 * i + 3] + bhh[4 * i + 3];
        g_bias4[i] = v;
    }
}

// ---------------- phase 1: xg[r][g] = bias[g] + sum_d x[r][d] * W_ih[g][d] ----------------
// grid 4096 blocks x 416 threads; block does 64 rows x 400 gates.
// thread (rg = tid/104, j = tid%104): 16 rows x 4 gates, f32x2 math, x via LDS.128.
__global__ __launch_bounds__(416, 1) void xgemm_kernel(const float* __restrict__ x) {
    extern __shared__ char smem[];
    float4* sW4 = (float4*)smem;                       // 64*104 float4 = 106496 B
    ULL*    sxd = (ULL*)(smem + 64 * 104 * 16);        // 64*64 dup pairs = 32768 B

    int tid = threadIdx.x;
    for (int i = tid; i < 64 * 104; i += 416) sW4[i] = g_W4ih[i];
    const float* xb = x + (size_t)blockIdx.x * (64 * 64);
    for (int i = tid; i < 64 * 64; i += 416) { float v = xb[i]; sxd[i] = pk(v, v); }
    __syncthreads();

    int rg = tid / 104;
    int j  = tid % 104;

    ULL acc01[16], acc23[16];
#pragma unroll
    for (int r = 0; r < 16; r++) { acc01[r] = 0ull; acc23[r] = 0ull; }

    const ulonglong2* xr = (const ulonglong2*)(sxd + rg * 16 * 64);  // row stride 32 ull2
#pragma unroll 2
    for (int k2 = 0; k2 < 32; k2++) {
        float4 wv0 = sW4[(2 * k2)     * 104 + j];
        float4 wv1 = sW4[(2 * k2 + 1) * 104 + j];
        ULL w01a = pk(wv0.x, wv0.y), w23a = pk(wv0.z, wv0.w);
        ULL w01b = pk(wv1.x, wv1.y), w23b = pk(wv1.z, wv1.w);
#pragma unroll
        for (int r = 0; r < 16; r++) {
            ulonglong2 xv = xr[r * 32 + k2];   // dup pairs for k=2k2, 2k2+1
            acc01[r] = fma2(w01a, xv.x, acc01[r]);
            acc23[r] = fma2(w23a, xv.x, acc23[r]);
            acc01[r] = fma2(w01b, xv.y, acc01[r]);
            acc23[r] = fma2(w23b, xv.y, acc23[r]);
        }
    }
    if (j < 100) {
        float4 bv = g_bias4[j];
        size_t row0 = (size_t)blockIdx.x * 64 + rg * 16;
#pragma unroll
        for (int r = 0; r < 16; r++) {
            float2 a = upk(acc01[r]);
            float2 b = upk(acc23[r]);
            float4 o = make_float4(a.x + bv.x, a.y + bv.y, b.x + bv.z, b.y + bv.w);
            *(float4*)(g_xg + (row0 + r) * 400 + 4 * j) = o;
        }
    }
}

// ---------------- phase 2: sequential LSTM recurrence + fused FC head ----------------
// 128 blocks x 224 threads; block owns batches (2*blk, 2*blk+1).
// W_hh lives ENTIRELY IN REGISTERS: thread j<200 holds 100 ULL pairs
// (W_hh[2j][k], W_hh[2j+1][k]) for k=0..99 (200 regs). Per step the only SMEM
// traffic is the h broadcast (LDS.128, two dup pairs per load) and the gate
// exchange — ~4x less crossbar traffic than the SMEM-weight version.
__global__ __launch_bounds__(224, 1) void lstm_kernel(const float* __restrict__ h0,
                                                      const float* __restrict__ c0,
                                                      const float* __restrict__ Wfc,
                                                      const float* __restrict__ bfc,
                                                      float* __restrict__ out) {
    __shared__ __align__(16) ULL   shd0[100];   // h batch0 duplicated pairs
    __shared__ __align__(16) ULL   shd1[100];   // h batch1 duplicated pairs
    __shared__ float gs[2 * 400];               // gates [2][400]
    __shared__ float red[2];                    // FC reduction

    const int t  = threadIdx.x;
    const int b0 = blockIdx.x * 2;

    if (t < 2) red[t] = 0.f;

    const int ub = (t < 100) ? 0 : 1;
    const int uu = t - ub * 100;

    // resident W_hh slice: 100 packed pairs -> 200 registers
    ULL w[100];
    if (t < 200) {
#pragma unroll
        for (int k = 0; k < 100; k++) w[k] = g_W2hh[k * 200 + t];
    }

    float c_reg = 0.f, h_last = 0.f;
    if (t < 200) {
        float hv = h0[(b0 + ub) * 100 + uu];
        c_reg    = c0[(b0 + ub) * 100 + uu];
        (ub ? shd1 : shd0)[uu] = pk(hv, hv);
    }
    __syncthreads();

    const float* xp0 = g_xg + (size_t)(b0)     * 1024 * 400 + 2 * t;
    const float* xp1 = g_xg + (size_t)(b0 + 1) * 1024 * 400 + 2 * t;
    float2 px0 = make_float2(0.f, 0.f), px1 = make_float2(0.f, 0.f);
    if (t < 200) { px0 = *(const float2*)xp0; px1 = *(const float2*)xp1; }

    for (int step = 0; step < 1024; step++) {
        if (t < 200) {
            ULL a0 = pk(px0.x, px0.y);   // xg init already includes biases
            ULL a1 = pk(px1.x, px1.y);
            if (step < 1023) {           // prefetch next step's xg (hides DRAM latency)
                px0 = *(const float2*)(xp0 + (size_t)(step + 1) * 400);
                px1 = *(const float2*)(xp1 + (size_t)(step + 1) * 400);
            }
            const ulonglong2* p0 = (const ulonglong2*)shd0;
            const ulonglong2* p1 = (const ulonglong2*)shd1;
#pragma unroll
            for (int k2 = 0; k2 < 50; k2++) {
                ulonglong2 hv0 = p0[k2];          // (h0[2k2] dup, h0[2k2+1] dup)
                ulonglong2 hv1 = p1[k2];
                a0 = fma2(w[2 * k2],     hv0.x, a0);
                a1 = fma2(w[2 * k2],     hv1.x, a1);
                a0 = fma2(w[2 * k2 + 1], hv0.y, a0);
                a1 = fma2(w[2 * k2 + 1], hv1.y, a1);
            }
            ((float2*)gs)[t]       = upk(a0);   // gates[b0][2t..2t+1]
            ((float2*)gs)[200 + t] = upk(a1);   // gates[b1][2t..2t+1]
        }
        __syncthreads();
        if (t < 200) {
            const float* gb = gs + ub * 400;
            float gi = gb[uu], gf = gb[100 + uu], gg = gb[200 + uu], go = gb[300 + uu];
            float i_ = sigf(gi);
            float f_ = sigf(gf);
            float g_ = tahf(gg);
            float o_ = sigf(go);
            c_reg = f_ * c_reg + i_ * g_;
            float h = o_ * tahf(c_reg);
            h_last = h;
            (ub ? shd1 : shd0)[uu] = pk(h, h);
        }
        __syncthreads();
    }

    // fused FC head: out[b] = dot(h_T[b], W_fc) + b_fc
    if (t < 200) atomicAdd(&red[ub], h_last * Wfc[uu]);
    __syncthreads();
    if (t < 2) out[b0 + t] = red[t] + bfc[0];
}

// ---------------- launch ----------------
extern "C" void kernel_launch(void* const* d_in, const int* in_sizes, int n_in,
                              void* d_out, int out_size) {
    const float* x   = (const float*)d_in[0];
    const float* h0  = (const float*)d_in[1];
    const float* c0  = (const float*)d_in[2];
    const float* Wih = (const float*)d_in[3];
    const float* Whh = (const float*)d_in[4];
    const float* bih = (const float*)d_in[5];
    const float* bhh = (const float*)d_in[6];
    const float* Wfc = (const float*)d_in[7];
    const float* bfc = (const float*)d_in[8];
    float* out = (float*)d_out;

    cudaFuncSetAttribute(xgemm_kernel, cudaFuncAttributeMaxDynamicSharedMemorySize, 139264);

    prep_kernel<<<64, 256>>>(Wih, Whh, bih, bhh);
    xgemm_kernel<<<4096, 416, 139264>>>(x);
    lstm_kernel<<<128, 224>>>(h0, c0, Wfc, bfc, out);
}

// round 7
// speedup vs baseline: 1.5761x; 1.0853x over previous
#include <cuda_runtime.h>

#define ULL unsigned long long

// ---------------- scratch (static device globals; no dynamic alloc) ----------------
__device__ float  g_xg[104857600];      // [256][1024][400] precomputed input gates (+bias)
__device__ ULL    g_W2hh[100 * 200];    // [k][j] packed pairs (W_hh[2j][k], W_hh[2j+1][k])
__device__ float4 g_W4ih[64 * 104];     // [k][j] (W_ih[4j+c][k]); j in [100,104) zero pad
__device__ float4 g_bias4[100];         // (b_ih + b_hh) grouped by 4

// ---------------- f32x2 packed-FMA helpers (Blackwell FFMA2) ----------------
__device__ __forceinline__ ULL pk(float x, float y) {
    ULL r; asm("mov.b64 %0,{%1,%2};" : "=l"(r) : "f"(x), "f"(y)); return r;
}
__device__ __forceinline__ float2 upk(ULL v) {
    float2 r; asm("mov.b64 {%0,%1},%2;" : "=f"(r.x), "=f"(r.y) : "l"(v)); return r;
}
__device__ __forceinline__ ULL fma2(ULL a, ULL b, ULL c) {
    ULL d; asm("fma.rn.f32x2 %0,%1,%2,%3;" : "=l"(d) : "l"(a), "l"(b), "l"(c)); return d;
}

__device__ __forceinline__ float sigf(float x) {
    float e = __expf(-x);
    return __fdividef(1.f, 1.f + e);
}
__device__ __forceinline__ float tahf(float x) {
    float e = __expf(2.f * x);
    return 1.f - __fdividef(2.f, e + 1.f);
}

// ---------------- prep: repack weights into GEMM-friendly layouts ----------------
__global__ void prep_kernel(const float* __restrict__ Wih, const float* __restrict__ Whh,
                            const float* __restrict__ bih, const float* __restrict__ bhh) {
    int tid = blockIdx.x * blockDim.x + threadIdx.x;
    int stride = gridDim.x * blockDim.x;
    for (int i = tid; i < 100 * 200; i += stride) {
        int k = i / 200, j = i % 200;
        g_W2hh[i] = pk(Whh[(2 * j) * 100 + k], Whh[(2 * j + 1) * 100 + k]);
    }
    for (int i = tid; i < 64 * 104; i += stride) {
        int k = i / 104, j = i % 104;
        float4 v = make_float4(0.f, 0.f, 0.f, 0.f);
        if (j < 100) {
            v.x = Wih[(4 * j + 0) * 64 + k];
            v.y = Wih[(4 * j + 1) * 64 + k];
            v.z = Wih[(4 * j + 2) * 64 + k];
            v.w = Wih[(4 * j + 3) * 64 + k];
        }
        g_W4ih[i] = v;
    }
    for (int i = tid; i < 100; i += stride) {
        float4 v;
        v.x = bih[4 * i + 0] + bhh[4 * i + 0];
        v.y = bih[4 * i + 1] + bhh[4 * i + 1];
        v.z = bih[4 * i + 2] + bhh[4 * i + 2];
        v.w = bih[4 * i + 3] + bhh[4 * i + 3];
        g_bias4[i] = v;
    }
}

// ---------------- phase 1: xg[r][g] = bias[g] + sum_d x[r][d] * W_ih[g][d] ----------------
// grid 4096 blocks x 416 threads; block does 64 rows x 400 gates.
__global__ __launch_bounds__(416, 1) void xgemm_kernel(const float* __restrict__ x) {
    extern __shared__ char smem[];
    float4* sW4 = (float4*)smem;                       // 64*104 float4 = 106496 B
    ULL*    sxd = (ULL*)(smem + 64 * 104 * 16);        // 64*64 dup pairs = 32768 B

    int tid = threadIdx.x;
    for (int i = tid; i < 64 * 104; i += 416) sW4[i] = g_W4ih[i];
    const float* xb = x + (size_t)blockIdx.x * (64 * 64);
    for (int i = tid; i < 64 * 64; i += 416) { float v = xb[i]; sxd[i] = pk(v, v); }
    __syncthreads();

    int rg = tid / 104;
    int j  = tid % 104;

    ULL acc01[16], acc23[16];
#pragma unroll
    for (int r = 0; r < 16; r++) { acc01[r] = 0ull; acc23[r] = 0ull; }

    const ulonglong2* xr = (const ulonglong2*)(sxd + rg * 16 * 64);  // row stride 32 ull2
#pragma unroll 2
    for (int k2 = 0; k2 < 32; k2++) {
        float4 wv0 = sW4[(2 * k2)     * 104 + j];
        float4 wv1 = sW4[(2 * k2 + 1) * 104 + j];
        ULL w01a = pk(wv0.x, wv0.y), w23a = pk(wv0.z, wv0.w);
        ULL w01b = pk(wv1.x, wv1.y), w23b = pk(wv1.z, wv1.w);
#pragma unroll
        for (int r = 0; r < 16; r++) {
            ulonglong2 xv = xr[r * 32 + k2];
            acc01[r] = fma2(w01a, xv.x, acc01[r]);
            acc23[r] = fma2(w23a, xv.x, acc23[r]);
            acc01[r] = fma2(w01b, xv.y, acc01[r]);
            acc23[r] = fma2(w23b, xv.y, acc23[r]);
        }
    }
    if (j < 100) {
        float4 bv = g_bias4[j];
        size_t row0 = (size_t)blockIdx.x * 64 + rg * 16;
#pragma unroll
        for (int r = 0; r < 16; r++) {
            float2 a = upk(acc01[r]);
            float2 b = upk(acc23[r]);
            float4 o = make_float4(a.x + bv.x, a.y + bv.y, b.x + bv.z, b.y + bv.w);
            *(float4*)(g_xg + (row0 + r) * 400 + 4 * j) = o;
        }
    }
}

// ---------------- phase 2: sequential LSTM recurrence + fused FC head ----------------
// 128 blocks x 512 threads (16 warps = 4/SMSP, balanced). Block owns batches
// (2*blk, 2*blk+1). Thread (kk = t/100 in [0,5), j = t%100) computes the
// partial matvec for gate QUAD (4j..4j+3), k-slice [20*kk, 20*kk+20), for
// BOTH batches. W_hh slice lives in 80 registers. h is stored in SMEM as
// dual-batch interleaved dup-pairs: one LDS.128 per k serves both batches.
// Pointwise threads (t<200) reduce the 5 k-partials + xg (prefetched from
// DRAM one step ahead) and run the cell update. 2 barriers/step.
__global__ __launch_bounds__(512, 1) void lstm_kernel(const float* __restrict__ h0,
                                                      const float* __restrict__ c0,
                                                      const float* __restrict__ Wfc,
                                                      const float* __restrict__ bfc,
                                                      float* __restrict__ out) {
    __shared__ __align__(16) ULL shi[200];        // [k][b]: shi[2k+b] = pk(h_b[k], h_b[k])
    __shared__ float part[5 * 2 * 400];           // [kk][b][gate] partial sums
    __shared__ float red[2];                      // FC reduction

    const int t  = threadIdx.x;
    const int b0 = blockIdx.x * 2;

    const bool mv = (t < 500);
    const int kk = t / 100;          // k-slice id (valid when mv)
    const int j  = t % 100;          // gate quad id
    const int k0 = kk * 20;

    // resident W_hh slice: 20 k x 2 pairs = 40 ULL = 80 registers
    ULL w01[20], w23[20];
    if (mv) {
#pragma unroll
        for (int kc = 0; kc < 20; kc++) {
            w01[kc] = g_W2hh[(k0 + kc) * 200 + 2 * j];
            w23[kc] = g_W2hh[(k0 + kc) * 200 + 2 * j + 1];
        }
    }

    const int ub = (t < 100) ? 0 : 1;   // pointwise role (t<200)
    const int uu = t - ub * 100;

    if (t < 2) red[t] = 0.f;

    float c_reg = 0.f, h_last = 0.f;
    float pxi = 0.f, pxf = 0.f, pxg = 0.f, pxo = 0.f;
    const float* xgb = g_xg;  // set properly below for t<200
    if (t < 200) {
        float hv = h0[(b0 + ub) * 100 + uu];
        c_reg    = c0[(b0 + ub) * 100 + uu];
        shi[2 * uu + ub] = pk(hv, hv);
        xgb = g_xg + (size_t)(b0 + ub) * 1024 * 400 + uu;
        pxi = xgb[0];
        pxf = xgb[100];
        pxg = xgb[200];
        pxo = xgb[300];
    }
    __syncthreads();

    float* pbase0 = part + (kk * 2 + 0) * 400 + 4 * j;
    float* pbase1 = part + (kk * 2 + 1) * 400 + 4 * j;
    const ulonglong2* hp = ((const ulonglong2*)shi) + k0;

    for (int step = 0; step < 1024; step++) {
        if (mv) {
            ULL a01_0 = 0ull, a23_0 = 0ull, a01_1 = 0ull, a23_1 = 0ull;
#pragma unroll
            for (int kc = 0; kc < 20; kc++) {
                ulonglong2 hv = hp[kc];            // (b0 dup pair, b1 dup pair), broadcast
                a01_0 = fma2(w01[kc], hv.x, a01_0);
                a23_0 = fma2(w23[kc], hv.x, a23_0);
                a01_1 = fma2(w01[kc], hv.y, a01_1);
                a23_1 = fma2(w23[kc], hv.y, a23_1);
            }
            float2 p01 = upk(a01_0), p23 = upk(a23_0);
            *(float4*)pbase0 = make_float4(p01.x, p01.y, p23.x, p23.y);
            p01 = upk(a01_1); p23 = upk(a23_1);
            *(float4*)pbase1 = make_float4(p01.x, p01.y, p23.x, p23.y);
        }
        __syncthreads();
        if (t < 200) {
            const float* pb = part + ub * 400;
            float gi = pxi, gf = pxf, gg = pxg, go = pxo;
#pragma unroll
            for (int kp = 0; kp < 5; kp++) {
                const float* p = pb + kp * 800;
                gi += p[uu];
                gf += p[100 + uu];
                gg += p[200 + uu];
                go += p[300 + uu];
            }
            if (step < 1023) {                     // prefetch next step's xg (DRAM hidden by matvec)
                const float* xn = xgb + (size_t)(step + 1) * 400;
                pxi = xn[0]; pxf = xn[100]; pxg = xn[200]; pxo = xn[300];
            }
            float i_ = sigf(gi);
            float f_ = sigf(gf);
            float g_ = tahf(gg);
            float o_ = sigf(go);
            c_reg = f_ * c_reg + i_ * g_;
            float h = o_ * tahf(c_reg);
            h_last = h;
            shi[2 * uu + ub] = pk(h, h);
        }
        __syncthreads();
    }

    // fused FC head: out[b] = dot(h_T[b], W_fc) + b_fc
    if (t < 200) atomicAdd(&red[ub], h_last * Wfc[uu]);
    __syncthreads();
    if (t < 2) out[b0 + t] = red[t] + bfc[0];
}

// ---------------- launch ----------------
extern "C" void kernel_launch(void* const* d_in, const int* in_sizes, int n_in,
                              void* d_out, int out_size) {
    const float* x   = (const float*)d_in[0];
    const float* h0  = (const float*)d_in[1];
    const float* c0  = (const float*)d_in[2];
    const float* Wih = (const float*)d_in[3];
    const float* Whh = (const float*)d_in[4];
    const float* bih = (const float*)d_in[5];
    const float* bhh = (const float*)d_in[6];
    const float* Wfc = (const float*)d_in[7];
    const float* bfc = (const float*)d_in[8];
    float* out = (float*)d_out;

    cudaFuncSetAttribute(xgemm_kernel, cudaFuncAttributeMaxDynamicSharedMemorySize, 139264);

    prep_kernel<<<64, 256>>>(Wih, Whh, bih, bhh);
    xgemm_kernel<<<4096, 416, 139264>>>(x);
    lstm_kernel<<<128, 512>>>(h0, c0, Wfc, bfc, out);
}